// round 12
// baseline (speedup 1.0000x reference)
#include <cuda_runtime.h>

// Problem constants (from reference)
constexpr int POOL     = 7;
constexpr int NUM_ROIS = 300;
constexpr int Wf       = 200;
constexpr int C        = 512;
constexpr int C4       = C / 4;                   // 128 float4 per pixel
constexpr int CELLS    = POOL * POOL;             // 49
constexpr int NCELLS   = NUM_ROIS * CELLS;        // 14700 (roi,cell) tiles

// One warp per (roi, cell). Each thread produces 4 output float4
// (c4 = lane, lane+32, lane+64, lane+96) -> 16 independent LDG.128
// front-batched for maximum memory-level parallelism.
// 14700 warps; 14700 % 8 != 0, so launch ceil(14700/8)=1838 blocks w/ guard.

__device__ __forceinline__ float4 bilerp4(float4 a, float4 b, float4 c, float4 d,
                                          float gx, float fx, float gy, float fy)
{
    float4 o;
    o.x = (a.x * gx + b.x * fx) * gy + (c.x * gx + d.x * fx) * fy;
    o.y = (a.y * gx + b.y * fx) * gy + (c.y * gx + d.y * fx) * fy;
    o.z = (a.z * gx + b.z * fx) * gy + (c.z * gx + d.z * fx) * fy;
    o.w = (a.w * gx + b.w * fx) * gy + (c.w * gx + d.w * fx) * fy;
    return o;
}

__global__ __launch_bounds__(256)
void roi_pool_kernel(const float4* __restrict__ feat4,
                     const int4*  __restrict__ rois,
                     float4*      __restrict__ out4)
{
    const int cellIdx = (blockIdx.x * 256 + threadIdx.x) >> 5;  // roi*49 + cell
    if (cellIdx >= NCELLS) return;                              // tail guard
    const int lane    = threadIdx.x & 31;

    const int roi  = cellIdx / CELLS;
    const int cell = cellIdx - roi * CELLS;
    const int py   = cell / POOL;
    const int px   = cell - py * POOL;

    const int4 r = __ldg(&rois[roi]);
    const int x0 = r.x, y0 = r.y, w = r.z, h = r.w;

    // Match reference: sy = py * (h/7), sx = px * (w/7) in fp32
    const float hs = (float)h / (float)POOL;
    const float ws = (float)w / (float)POOL;
    const float sy = (float)py * hs;
    const float sx = (float)px * ws;

    const int y_lo = (int)floorf(sy);
    const int x_lo = (int)floorf(sx);
    const int y_hi = min(y_lo + 1, h - 1);
    const int x_hi = min(x_lo + 1, w - 1);

    const float fy = sy - (float)y_lo;
    const float fx = sx - (float)x_lo;
    const float gy = 1.0f - fy;
    const float gx = 1.0f - fx;

    // Absolute pixel base offsets (in float4 units), lane folded in
    const int p00 = ((y0 + y_lo) * Wf + (x0 + x_lo)) * C4 + lane;
    const int p01 = ((y0 + y_lo) * Wf + (x0 + x_hi)) * C4 + lane;
    const int p10 = ((y0 + y_hi) * Wf + (x0 + x_lo)) * C4 + lane;
    const int p11 = ((y0 + y_hi) * Wf + (x0 + x_hi)) * C4 + lane;

    // 16 independent 16B loads — all issued before any consumption.
    const float4 a00 = feat4[p00];       // chunk 0: c4 = lane
    const float4 a01 = feat4[p01];
    const float4 a10 = feat4[p10];
    const float4 a11 = feat4[p11];
    const float4 b00 = feat4[p00 + 32];  // chunk 1
    const float4 b01 = feat4[p01 + 32];
    const float4 b10 = feat4[p10 + 32];
    const float4 b11 = feat4[p11 + 32];
    const float4 c00 = feat4[p00 + 64];  // chunk 2
    const float4 c01 = feat4[p01 + 64];
    const float4 c10 = feat4[p10 + 64];
    const float4 c11 = feat4[p11 + 64];
    const float4 d00 = feat4[p00 + 96];  // chunk 3
    const float4 d01 = feat4[p01 + 96];
    const float4 d10 = feat4[p10 + 96];
    const float4 d11 = feat4[p11 + 96];

    const float4 oa = bilerp4(a00, a01, a10, a11, gx, fx, gy, fy);
    const float4 ob = bilerp4(b00, b01, b10, b11, gx, fx, gy, fy);
    const float4 oc = bilerp4(c00, c01, c10, c11, gx, fx, gy, fy);
    const float4 od = bilerp4(d00, d01, d10, d11, gx, fx, gy, fy);

    // Streaming stores: output is write-once; keep feat resident in L2.
    const int obase = cellIdx * C4 + lane;
    __stcs(&out4[obase],      oa);
    __stcs(&out4[obase + 32], ob);
    __stcs(&out4[obase + 64], oc);
    __stcs(&out4[obase + 96], od);
}

extern "C" void kernel_launch(void* const* d_in, const int* in_sizes, int n_in,
                              void* d_out, int out_size)
{
    const float4* feat4 = (const float4*)d_in[0];   // (1, 200, 200, 512) f32
    const int4*   rois  = (const int4*)d_in[1];     // (1, 300, 4) int32
    float4*       out4  = (float4*)d_out;           // (1, 300, 7, 7, 512) f32

    constexpr int WARPS  = NCELLS;                  // 14700
    constexpr int BLOCKS = (WARPS + 7) / 8;         // 1838 blocks, 8 warps each
    roi_pool_kernel<<<BLOCKS, 256>>>(feat4, rois, out4);
}

// round 17
// speedup vs baseline: 1.0243x; 1.0243x over previous
#include <cuda_runtime.h>

// Problem constants (from reference)
constexpr int POOL     = 7;
constexpr int NUM_ROIS = 300;
constexpr int Wf       = 200;
constexpr int C        = 512;
constexpr int C4       = C / 4;                   // 128 float4 per pixel
constexpr int CELLS    = POOL * POOL;             // 49
constexpr int NCELLS   = NUM_ROIS * CELLS;        // 14700 (roi,cell) tiles

// One warp per (roi, cell), ILP=4: each thread produces 4 output float4
// (c4 = lane, +32, +64, +96). The 16 gather loads are emitted as asm volatile
// ld.global.nc.v4.f32 with distinct destination registers so ptxas MUST
// front-batch all 16 LDG.128 (8 KB in flight per warp) before any FMA.
// 128-thread blocks: 14700 warps / 4 = 3675 blocks exactly — no tail.

#define LDG4(dst, ptr, byteoff)                                          \
    asm volatile("ld.global.nc.v4.f32 {%0,%1,%2,%3}, [%4+" #byteoff "];" \
                 : "=f"(dst.x), "=f"(dst.y), "=f"(dst.z), "=f"(dst.w)    \
                 : "l"(ptr))

__device__ __forceinline__ float4 bilerp4(float4 a, float4 b, float4 c, float4 d,
                                          float gx, float fx, float gy, float fy)
{
    float4 o;
    o.x = (a.x * gx + b.x * fx) * gy + (c.x * gx + d.x * fx) * fy;
    o.y = (a.y * gx + b.y * fx) * gy + (c.y * gx + d.y * fx) * fy;
    o.z = (a.z * gx + b.z * fx) * gy + (c.z * gx + d.z * fx) * fy;
    o.w = (a.w * gx + b.w * fx) * gy + (c.w * gx + d.w * fx) * fy;
    return o;
}

__global__ __launch_bounds__(128)
void roi_pool_kernel(const float4* __restrict__ feat4,
                     const int4*  __restrict__ rois,
                     float4*      __restrict__ out4)
{
    const int cellIdx = (blockIdx.x * 128 + threadIdx.x) >> 5;  // roi*49 + cell
    const int lane    = threadIdx.x & 31;

    const int roi  = cellIdx / CELLS;
    const int cell = cellIdx - roi * CELLS;
    const int py   = cell / POOL;
    const int px   = cell - py * POOL;

    const int4 r = __ldg(&rois[roi]);
    const int x0 = r.x, y0 = r.y, w = r.z, h = r.w;

    // Match reference: sy = py * (h/7), sx = px * (w/7) in fp32
    const float hs = (float)h / (float)POOL;
    const float ws = (float)w / (float)POOL;
    const float sy = (float)py * hs;
    const float sx = (float)px * ws;

    const int y_lo = (int)floorf(sy);
    const int x_lo = (int)floorf(sx);
    const int y_hi = min(y_lo + 1, h - 1);
    const int x_hi = min(x_lo + 1, w - 1);

    const float fy = sy - (float)y_lo;
    const float fx = sx - (float)x_lo;
    const float gy = 1.0f - fy;
    const float gx = 1.0f - fx;

    // Corner base pointers (lane folded in)
    const float4* q00 = feat4 + ((y0 + y_lo) * Wf + (x0 + x_lo)) * C4 + lane;
    const float4* q01 = feat4 + ((y0 + y_lo) * Wf + (x0 + x_hi)) * C4 + lane;
    const float4* q10 = feat4 + ((y0 + y_hi) * Wf + (x0 + x_lo)) * C4 + lane;
    const float4* q11 = feat4 + ((y0 + y_hi) * Wf + (x0 + x_hi)) * C4 + lane;

    // 16 front-batched LDG.128 — asm volatile with distinct dest regs
    // forbids register reuse / interleaved consumption.
    float4 a00, a01, a10, a11;   // chunk 0: +0B
    float4 b00, b01, b10, b11;   // chunk 1: +512B (32 float4)
    float4 c00, c01, c10, c11;   // chunk 2: +1024B
    float4 d00, d01, d10, d11;   // chunk 3: +1536B
    LDG4(a00, q00, 0);    LDG4(a01, q01, 0);    LDG4(a10, q10, 0);    LDG4(a11, q11, 0);
    LDG4(b00, q00, 512);  LDG4(b01, q01, 512);  LDG4(b10, q10, 512);  LDG4(b11, q11, 512);
    LDG4(c00, q00, 1024); LDG4(c01, q01, 1024); LDG4(c10, q10, 1024); LDG4(c11, q11, 1024);
    LDG4(d00, q00, 1536); LDG4(d01, q01, 1536); LDG4(d10, q10, 1536); LDG4(d11, q11, 1536);

    const float4 oa = bilerp4(a00, a01, a10, a11, gx, fx, gy, fy);
    const float4 ob = bilerp4(b00, b01, b10, b11, gx, fx, gy, fy);
    const float4 oc = bilerp4(c00, c01, c10, c11, gx, fx, gy, fy);
    const float4 od = bilerp4(d00, d01, d10, d11, gx, fx, gy, fy);

    // Streaming stores: output is write-once; keep feat resident in L2.
    const int obase = cellIdx * C4 + lane;
    __stcs(&out4[obase],      oa);
    __stcs(&out4[obase + 32], ob);
    __stcs(&out4[obase + 64], oc);
    __stcs(&out4[obase + 96], od);
}

extern "C" void kernel_launch(void* const* d_in, const int* in_sizes, int n_in,
                              void* d_out, int out_size)
{
    const float4* feat4 = (const float4*)d_in[0];   // (1, 200, 200, 512) f32
    const int4*   rois  = (const int4*)d_in[1];     // (1, 300, 4) int32
    float4*       out4  = (float4*)d_out;           // (1, 300, 7, 7, 512) f32

    constexpr int BLOCKS = NCELLS / 4;              // 3675 blocks, 4 warps each
    roi_pool_kernel<<<BLOCKS, 128>>>(feat4, rois, out4);
}